// round 2
// baseline (speedup 1.0000x reference)
#include <cuda_runtime.h>

#define TPB 256
#define CELLS_PER_BLOCK 256
#define MAX_BLOCKS 16384

// Per-block partials: [nobj_count, reg, conf, noobj_sq, cls]  (padded to 6)
__device__ float g_partials[MAX_BLOCKS * 6];
// objmap dtype flag: 0 = bool bytes, 1 = int32, 2 = float32
__device__ int g_objflag;

__global__ void detect_objdtype_kernel(const unsigned int* __restrict__ p, int nwords)
{
    const int tid = threadIdx.x;
    bool isf = false, big = false;
    for (int i = tid; i < nwords; i += TPB) {
        unsigned int w = p[i];
        if (w == 0x3F800000u) isf = true;
        else if (w > 1u) big = true;   // multi-byte/bit pattern -> packed bool bytes
    }
    __shared__ int s_isf, s_big;
    if (tid == 0) { s_isf = 0; s_big = 0; }
    __syncthreads();
    if (isf) atomicOr(&s_isf, 1);
    if (big) atomicOr(&s_big, 1);
    __syncthreads();
    if (tid == 0) g_objflag = s_isf ? 2 : (s_big ? 0 : 1);
}

__device__ __forceinline__ float load_obj(const void* objmap, int idx, int flag)
{
    if (flag == 2) return ((const float*)objmap)[idx];
    if (flag == 1) return (float)(((const int*)objmap)[idx] != 0);
    return ((const unsigned char*)objmap)[idx] ? 1.0f : 0.0f;
}

__device__ __forceinline__ float iou_pred_vs_tgt(
    float px, float py, float pw, float ph,
    float tx1, float ty1, float tx2, float ty2, float tarea)
{
    const float invS = 1.0f / 14.0f;
    float cx = px * invS, cy = py * invS;
    float x1 = cx - 0.5f * pw, y1 = cy - 0.5f * ph;
    float x2 = cx + 0.5f * pw, y2 = cy + 0.5f * ph;
    float lx = fmaxf(x1, tx1), ly = fmaxf(y1, ty1);
    float rx = fminf(x2, tx2), ry = fminf(y2, ty2);
    float wx = fmaxf(rx - lx, 0.0f), wy = fmaxf(ry - ly, 0.0f);
    float inter = wx * wy;
    float a1 = (x2 - x1) * (y2 - y1);
    return inter / (a1 + tarea - inter);
}

__global__ void __launch_bounds__(TPB)
yolo_reduce_kernel(const float* __restrict__ pred,
                   const float* __restrict__ tbox,
                   const float* __restrict__ tcls,
                   const void* __restrict__ objmap,
                   int n_cells)
{
    __shared__ float s_box[CELLS_PER_BLOCK * 10];
    __shared__ float s_obj[CELLS_PER_BLOCK];
    __shared__ float s_red[(TPB / 32) * 6];

    const int tid = threadIdx.x;
    const int cellbase = blockIdx.x * CELLS_PER_BLOCK;
    int cib = n_cells - cellbase;
    if (cib > CELLS_PER_BLOCK) cib = CELLS_PER_BLOCK;

    const int flag = g_objflag;

    // Load object map for this block's cells
    for (int c = tid; c < cib; c += TPB)
        s_obj[c] = load_obj(objmap, cellbase + c, flag);
    __syncthreads();

    // ---- Phase A: coalesced stream of pred (30 ch/cell) + target_cls ----
    float acc_cls = 0.0f, acc_noobj = 0.0f;
    const float* predb = pred + (size_t)cellbase * 30;
    const float* tclsb = tcls + (size_t)cellbase * 20;
    const int total = cib * 30;
    for (int f = tid; f < total; f += TPB) {
        float v = predb[f];
        int cell = f / 30;
        int ch = f - cell * 30;
        float obj = s_obj[cell];
        if (ch < 10) {
            s_box[cell * 10 + ch] = v;          // stash box channels for phase B
            acc_noobj += (1.0f - obj) * v * v;  // no-obj squared term (b1 & b2)
        } else {
            float t = tclsb[cell * 20 + (ch - 10)];
            float d = v - t;
            acc_cls += obj * d * d;             // class loss term
        }
    }
    __syncthreads();

    // ---- Phase B: per-cell box/IoU/reg/conf ----
    float acc_reg = 0.0f, acc_conf = 0.0f, acc_nobjcnt = 0.0f;
    if (tid < cib) {
        float obj = s_obj[tid];
        acc_nobjcnt = obj;
        if (obj > 0.0f) {
            const float invS = 1.0f / 14.0f;
            float4 tb = reinterpret_cast<const float4*>(tbox)[cellbase + tid];
            float tcx = tb.x * invS, tcy = tb.y * invS;
            float tx1 = tcx - 0.5f * tb.z, ty1 = tcy - 0.5f * tb.w;
            float tx2 = tcx + 0.5f * tb.z, ty2 = tcy + 0.5f * tb.w;
            float tarea = (tx2 - tx1) * (ty2 - ty1);

            const float* bb = &s_box[tid * 10];
            float b1x = bb[0], b1y = bb[1], b1w = bb[2], b1h = bb[3], b1c = bb[4];
            float b2x = bb[5], b2y = bb[6], b2w = bb[7], b2h = bb[8], b2c = bb[9];

            float iou1 = iou_pred_vs_tgt(b1x, b1y, b1w, b1h, tx1, ty1, tx2, ty2, tarea);
            float iou2 = iou_pred_vs_tgt(b2x, b2y, b2w, b2h, tx1, ty1, tx2, ty2, tarea);

            bool take1 = (iou1 >= iou2);
            float bx = take1 ? b1x : b2x;
            float by = take1 ? b1y : b2y;
            float bw = take1 ? b1w : b2w;
            float bh = take1 ? b1h : b2h;
            float bc = take1 ? b1c : b2c;
            float biou = take1 ? iou1 : iou2;

            float dx = bx - tb.x;
            float dy = by - tb.y;
            float dw = sqrtf(bw) - sqrtf(tb.z);
            float dh = sqrtf(bh) - sqrtf(tb.w);
            acc_reg = dx * dx + dy * dy + dw * dw + dh * dh;

            float dc = bc - biou;
            acc_conf = dc * dc;
        }
    }

    // ---- Block reduction of 5 accumulators ----
    float vals[5] = {acc_nobjcnt, acc_reg, acc_conf, acc_noobj, acc_cls};
    const int lane = tid & 31;
    const int wid = tid >> 5;
    #pragma unroll
    for (int k = 0; k < 5; k++) {
        float v = vals[k];
        #pragma unroll
        for (int off = 16; off > 0; off >>= 1)
            v += __shfl_down_sync(0xffffffffu, v, off);
        if (lane == 0) s_red[k * (TPB / 32) + wid] = v;
    }
    __syncthreads();
    if (tid == 0) {
        #pragma unroll
        for (int k = 0; k < 5; k++) {
            float v = 0.0f;
            #pragma unroll
            for (int w = 0; w < TPB / 32; w++) v += s_red[k * (TPB / 32) + w];
            g_partials[blockIdx.x * 6 + k] = v;
        }
    }
}

__global__ void __launch_bounds__(TPB)
yolo_final_kernel(int nblocks, int n_cells, float n_batch, float* __restrict__ out)
{
    __shared__ double s_red[TPB / 32];
    __shared__ double s_tot[5];

    const int tid = threadIdx.x;
    const int lane = tid & 31;
    const int wid = tid >> 5;

    double acc[5] = {0.0, 0.0, 0.0, 0.0, 0.0};
    for (int i = tid; i < nblocks; i += TPB) {
        #pragma unroll
        for (int k = 0; k < 5; k++)
            acc[k] += (double)g_partials[i * 6 + k];
    }

    #pragma unroll
    for (int k = 0; k < 5; k++) {
        double v = acc[k];
        #pragma unroll
        for (int off = 16; off > 0; off >>= 1)
            v += __shfl_down_sync(0xffffffffu, v, off);
        if (lane == 0) s_red[wid] = v;
        __syncthreads();
        if (tid == 0) {
            double t = 0.0;
            #pragma unroll
            for (int w = 0; w < TPB / 32; w++) t += s_red[w];
            s_tot[k] = t;
        }
        __syncthreads();
    }

    if (tid == 0) {
        double n_obj = s_tot[0];
        double n_noobj = (double)n_cells - n_obj;
        double reg_loss = 5.0 * s_tot[1] / n_obj;
        double conf_loss = s_tot[2] / n_obj;
        double noobj_loss = 0.5 * s_tot[3] / n_noobj;
        double cls_loss = s_tot[4] / (double)n_batch;
        double total = reg_loss + conf_loss + noobj_loss + cls_loss;
        out[0] = (float)total;
        out[1] = (float)reg_loss;
        out[2] = (float)conf_loss;
        out[3] = (float)noobj_loss;
        out[4] = (float)cls_loss;
    }
}

extern "C" void kernel_launch(void* const* d_in, const int* in_sizes, int n_in,
                              void* d_out, int out_size)
{
    const float* pred = (const float*)d_in[0];
    const float* tbox = (const float*)d_in[1];
    const float* tcls = (const float*)d_in[2];
    const void* objmap = d_in[3];
    float* out = (float*)d_out;

    const int n_cells = in_sizes[3];                 // N * S * S
    const int n_batch = in_sizes[0] / (14 * 14 * 30);
    int blocks = (n_cells + CELLS_PER_BLOCK - 1) / CELLS_PER_BLOCK;
    if (blocks > MAX_BLOCKS) blocks = MAX_BLOCKS;    // (not reachable at this shape)

    // Scan first 8 K words (32 KB) — safe even if objmap is 1-byte bool
    int nwords = n_cells / 4;
    if (nwords > 8192) nwords = 8192;
    detect_objdtype_kernel<<<1, TPB>>>((const unsigned int*)objmap, nwords);

    yolo_reduce_kernel<<<blocks, TPB>>>(pred, tbox, tcls, objmap, n_cells);
    yolo_final_kernel<<<1, TPB>>>(blocks, n_cells, (float)n_batch, out);
}